// round 2
// baseline (speedup 1.0000x reference)
#include <cuda_runtime.h>
#include <math.h>

#define Nn 4096
#define Ee 8192
#define Mm 128
#define ND 128
#define ED 64
#define PQ 16
#define LAYERS 4
#define TAU 0.25f
#define FRIC 0.1f

// ---------------- scratch (device globals; no allocation allowed) ----------------
__device__ float g_a[Nn], g_c[Nn], g_avt[Nn], g_avu[Nn];
__device__ int   g_mol[Nn];
__device__ float g_ev[Nn * ND];
__device__ float g_w[Ee];
__device__ float g_p[Nn * PQ], g_q[Nn * PQ], g_psum[Nn * PQ], g_qsum[Nn * PQ];
__device__ float g_y[Nn * PQ];
__device__ float g_su[Nn], g_st[Nn], g_g[Nn];
__device__ float g_Gm[Mm], g_Sm[Mm], g_h[Mm], g_d[Mm];
__device__ float g_S[LAYERS];
__device__ float g_cTotal;

__device__ __forceinline__ float warp_sum(float v) {
#pragma unroll
    for (int o = 16; o; o >>= 1) v += __shfl_xor_sync(0xffffffffu, v, o);
    return v;
}
__device__ __forceinline__ float sigmoidf(float x) { return 1.f / (1.f + expf(-x)); }
__device__ __forceinline__ float softplusf(float x) { return fmaxf(x, 0.f) + log1pf(expf(-fabsf(x))); }

// ---------------- A: per-node setup (warp/node) ----------------
// mol-id extraction, scalar dots a/c/Avt/Avu, p0 = tanh(v@Wp+bp), zero scratch.
__global__ void kA(const float* __restrict__ vf, const float* __restrict__ mnm,
                   const float* __restrict__ We, const float* __restrict__ Wp,
                   const float* __restrict__ bp, const float* __restrict__ Wt,
                   const float* __restrict__ Wu)
{
    int gw = (blockIdx.x * blockDim.x + threadIdx.x) >> 5;
    int lane = threadIdx.x & 31;
    if (gw >= Nn) return;
    int n = gw;
    float v0 = vf[n*ND+lane], v1 = vf[n*ND+lane+32], v2 = vf[n*ND+lane+64], v3 = vf[n*ND+lane+96];

    // molecule id: scan column n of mnm
    int mol = -1;
#pragma unroll
    for (int j = 0; j < 4; j++) {
        int m = lane + 32*j;
        if (mnm[(size_t)m * Nn + n] > 0.5f) mol = m;
    }
#pragma unroll
    for (int o = 16; o; o >>= 1) mol = max(mol, __shfl_xor_sync(0xffffffffu, mol, o));

    float sa = warp_sum(v0*We[lane]     + v1*We[lane+32]     + v2*We[lane+64]     + v3*We[lane+96]);
    float sc = warp_sum(v0*We[192+lane] + v1*We[192+lane+32] + v2*We[192+lane+64] + v3*We[192+lane+96]);
    float st = warp_sum(v0*Wt[lane]     + v1*Wt[lane+32]     + v2*Wt[lane+64]     + v3*Wt[lane+96]);
    float su = warp_sum(v0*Wu[lane]     + v1*Wu[lane+32]     + v2*Wu[lane+64]     + v3*Wu[lane+96]);

    float pk = 0.f;
#pragma unroll
    for (int k = 0; k < PQ; k++) {
        float s = warp_sum(v0*Wp[lane*PQ+k] + v1*Wp[(lane+32)*PQ+k] +
                           v2*Wp[(lane+64)*PQ+k] + v3*Wp[(lane+96)*PQ+k]);
        if (lane == k) pk = tanhf(s + bp[k]);
    }
    if (lane < PQ) {
        g_p[n*PQ+lane] = pk; g_psum[n*PQ+lane] = pk; g_y[n*PQ+lane] = 0.f;
    }
    if (lane == 0) {
        g_mol[n] = mol; g_a[n] = sa; g_c[n] = sc; g_avt[n] = st; g_avu[n] = su; g_g[n] = 0.f;
        if (n < Mm) { g_Gm[n] = 0.f; g_Sm[n] = 0.f; g_h[n] = 0.f; g_d[n] = 0.f; }
        if (n < LAYERS) g_S[n] = 0.f;
        if (n == 0) g_cTotal = 0.f;
    }
#pragma unroll
    for (int j = 0; j < 4; j++) g_ev[n*ND + lane + 32*j] = 0.f;
}

// ---------------- B: edge weights + scatter ev = e @ v_features (warp/edge) ----------------
__global__ void kB(const float* __restrict__ vf, const float* __restrict__ ef,
                   const int* __restrict__ us, const int* __restrict__ vs,
                   const float* __restrict__ We, const float* __restrict__ be)
{
    int gw = (blockIdx.x * blockDim.x + threadIdx.x) >> 5;
    int lane = threadIdx.x & 31;
    if (gw >= Ee) return;
    int e = gw;
    int u = us[e], v = vs[e];
    float s = ef[e*ED+lane]*We[128+lane] + ef[e*ED+32+lane]*We[160+lane];
    s = warp_sum(s);
    float w = sigmoidf(g_a[u] + g_c[v] + s + be[0]);
    if (lane == 0) g_w[e] = w;
#pragma unroll
    for (int j = 0; j < 4; j++) {
        int d = lane + 32*j;
        float xu = vf[u*ND+d], xv = vf[v*ND+d];
        if (u != v) {
            float t = w * (xu + xv);
            atomicAdd(&g_ev[u*ND+d], t);
            atomicAdd(&g_ev[v*ND+d], t);
        } else {
            atomicAdd(&g_ev[u*ND+d], w * xu);
        }
    }
}

// ---------------- C: q0 = tanh((e@v) @ Wq + bq) (warp/node) ----------------
__global__ void kC(const float* __restrict__ Wq, const float* __restrict__ bq)
{
    int gw = (blockIdx.x * blockDim.x + threadIdx.x) >> 5;
    int lane = threadIdx.x & 31;
    if (gw >= Nn) return;
    int n = gw;
    float e0 = g_ev[n*ND+lane], e1 = g_ev[n*ND+lane+32], e2 = g_ev[n*ND+lane+64], e3 = g_ev[n*ND+lane+96];
    float qk = 0.f;
#pragma unroll
    for (int k = 0; k < PQ; k++) {
        float s = warp_sum(e0*Wq[lane*PQ+k] + e1*Wq[(lane+32)*PQ+k] +
                           e2*Wq[(lane+64)*PQ+k] + e3*Wq[(lane+96)*PQ+k]);
        if (lane == k) qk = tanhf(s + bq[k]);
    }
    if (lane < PQ) { g_q[n*PQ+lane] = qk; g_qsum[n*PQ+lane] = qk; }
}

// ---------------- D: y = e @ q_cur (thread per edge*col) ----------------
__global__ void kD(const int* __restrict__ us, const int* __restrict__ vs)
{
    int idx = blockIdx.x * blockDim.x + threadIdx.x;
    if (idx >= Ee * PQ) return;
    int e = idx >> 4, k = idx & 15;
    int u = us[e], v = vs[e];
    float w = g_w[e];
    float qu = g_q[u*PQ+k], qv = g_q[v*PQ+k];
    if (u != v) {
        float t = w * (qu + qv);
        atomicAdd(&g_y[u*PQ+k], t);
        atomicAdd(&g_y[v*PQ+k], t);
    } else {
        atomicAdd(&g_y[u*PQ+k], w * qu);
    }
}

// ---------------- E: node pass: su, st (+ h,d at last layer; + c-reduce of prev layer) ----------------
__global__ void kE(const float* __restrict__ Wt, const float* __restrict__ Wu, int layer)
{
    int n = blockIdx.x * blockDim.x + threadIdx.x;  // exactly Nn threads
    float zu = g_avu[n], zt = g_avt[n];
#pragma unroll
    for (int k = 0; k < PQ; k++) {
        float yv = g_y[n*PQ+k];
        zu += yv * Wu[ND+k];
        zt += g_p[n*PQ+k] * Wt[ND+k];
        g_y[n*PQ+k] = 0.f;  // consumed; zero for next layer
    }
    float su = sigmoidf(zu), st = sigmoidf(zt);
    g_su[n] = su; g_st[n] = st; g_g[n] = 0.f;
    if (layer == LAYERS - 1) {
        int m = g_mol[n];
        atomicAdd(&g_h[m], softplusf(zt) + softplusf(zu));
        atomicAdd(&g_d[m], st * st);
    }
    // block 0 extra duty: finish previous layer's c-loss and reset mol sums
    if (layer > 0 && blockIdx.x == 0) {
        __shared__ float csum[8];
        int tid = threadIdx.x;
        float term = 0.f;
        if (tid < Mm) {
            float Gm = g_Gm[tid], Sm = g_Sm[tid];
            float nWu = 0.f, dTU = 0.f, nWt = 0.f;
#pragma unroll
            for (int k = 0; k < PQ; k++) { float a = Wu[ND+k], b = Wt[ND+k]; nWu += a*a; dTU += a*b; nWt += b*b; }
            term = Gm*Gm*nWu + 2.f*FRIC*Gm*Sm*dTU + FRIC*FRIC*Sm*Sm*nWt;
            g_Gm[tid] = 0.f; g_Sm[tid] = 0.f;
        }
        term = warp_sum(term);
        if ((tid & 31) == 0) csum[tid >> 5] = term;
        __syncthreads();
        if (tid == 0) {
            float s = 0.f;
            for (int i = 0; i < 8; i++) s += csum[i];
            g_cTotal += TAU * sqrtf(s);
        }
    }
}

// ---------------- F: g = e @ su (thread per edge) ----------------
__global__ void kF(const int* __restrict__ us, const int* __restrict__ vs)
{
    int e = blockIdx.x * blockDim.x + threadIdx.x;
    if (e >= Ee) return;
    int u = us[e], v = vs[e];
    float w = g_w[e];
    float su = g_su[u], sv = g_su[v];
    if (u != v) {
        float t = w * (su + sv);
        atomicAdd(&g_g[u], t);
        atomicAdd(&g_g[v], t);
    } else {
        atomicAdd(&g_g[u], w * su);
    }
}

// ---------------- G: p/q update, s-loss, mol sums (thread per node*col) ----------------
__global__ void kG(const float* __restrict__ Wt, const float* __restrict__ Wu, int layer)
{
    int idx = blockIdx.x * blockDim.x + threadIdx.x;  // exactly Nn*PQ threads
    int n = idx >> 4, k = idx & 15;
    float st = g_st[n], gg = g_g[n];
    float wt2 = Wt[ND+k], wu2 = Wu[ND+k];
    float gp = st * wt2, gq = gg * wu2;
    float dq = gp;
    float dp = -gq - FRIC * gp;
    float pold = g_p[idx];
    float diff = dq - pold;
    float pnew = pold + TAU * dp;
    float qnew = g_q[idx] + TAU * dq;
    g_p[idx] = pnew; g_q[idx] = qnew;
    g_psum[idx] += pnew; g_qsum[idx] += qnew;
    if (k == 0) {
        int m = g_mol[n];
        atomicAdd(&g_Gm[m], gg);
        atomicAdd(&g_Sm[m], st);
    }
    float d2 = warp_sum(diff * diff);
    __shared__ float sh[8];
    if ((threadIdx.x & 31) == 0) sh[threadIdx.x >> 5] = d2;
    __syncthreads();
    if (threadIdx.x == 0) {
        float s = 0.f;
        for (int i = 0; i < 8; i++) s += sh[i];
        atomicAdd(&g_S[layer], s);
    }
}

// ---------------- H: finalize outputs ----------------
__global__ void kH(float* __restrict__ out, const float* __restrict__ Wt, const float* __restrict__ Wu)
{
    int idx = blockIdx.x * blockDim.x + threadIdx.x;  // 2*Nn*PQ threads
    if (idx < Nn * PQ) out[idx] = g_psum[idx] * 0.2f;
    else               out[idx] = g_qsum[idx - Nn*PQ] * 0.2f;

    if (blockIdx.x == 0) {
        int tid = threadIdx.x;
        __shared__ float csum[8];
        float nWu = 0.f, dTU = 0.f, nWt = 0.f;
#pragma unroll
        for (int k = 0; k < PQ; k++) { float a = Wu[ND+k], b = Wt[ND+k]; nWu += a*a; dTU += a*b; nWt += b*b; }
        float term = 0.f;
        if (tid < Mm) {
            float Gm = g_Gm[tid], Sm = g_Sm[tid];
            term = Gm*Gm*nWu + 2.f*FRIC*Gm*Sm*dTU + FRIC*FRIC*Sm*Sm*nWt;
            out[2*Nn*PQ + 2 + tid]      = g_h[tid];        // h
            out[2*Nn*PQ + 2 + Mm + tid] = g_d[tid] * nWt;  // d
        }
        term = warp_sum(term);
        if ((tid & 31) == 0) csum[tid >> 5] = term;
        __syncthreads();
        if (tid == 0) {
            float s = 0.f;
            for (int i = 0; i < 8; i++) s += csum[i];
            float cT = g_cTotal + TAU * sqrtf(s);
            float sT = 0.f;
            for (int i = 0; i < LAYERS; i++) sT += sqrtf(g_S[i]);
            out[2*Nn*PQ + 0] = sT;
            out[2*Nn*PQ + 1] = cT;
        }
    }
}

extern "C" void kernel_launch(void* const* d_in, const int* in_sizes, int n_in,
                              void* d_out, int out_size)
{
    const float* vf  = (const float*)d_in[0];
    const float* ef  = (const float*)d_in[1];
    const int*   us  = (const int*)  d_in[2];
    const int*   vs  = (const int*)  d_in[3];
    const float* mnm = (const float*)d_in[4];
    // d_in[5] mol_node_mask (unused), d_in[6] node_edge_matrix (unused!), d_in[7] node_edge_mask (unused)
    const float* We  = (const float*)d_in[8];
    const float* be  = (const float*)d_in[9];
    const float* Wp  = (const float*)d_in[10];
    const float* bp  = (const float*)d_in[11];
    const float* Wq  = (const float*)d_in[12];
    const float* bq  = (const float*)d_in[13];
    const float* Wt  = (const float*)d_in[14];
    const float* Wu  = (const float*)d_in[15];
    float* out = (float*)d_out;

    kA<<<512, 256>>>(vf, mnm, We, Wp, bp, Wt, Wu);
    kB<<<1024, 256>>>(vf, ef, us, vs, We, be);
    kC<<<512, 256>>>(Wq, bq);
    for (int i = 0; i < LAYERS; i++) {
        kD<<<512, 256>>>(us, vs);
        kE<<<16, 256>>>(Wt, Wu, i);
        kF<<<32, 256>>>(us, vs);
        kG<<<256, 256>>>(Wt, Wu, i);
    }
    kH<<<512, 256>>>(out, Wt, Wu);
}